// round 12
// baseline (speedup 1.0000x reference)
#include <cuda_runtime.h>
#include <cstdint>

#define NBLK 444    // 148 SMs * 3 CTAs of 512 threads — 48 warps/SM, one wave
#define NTHR 512

// Per-block partials — every slot written on every call; no zeroing needed.
__device__ float        g_psum[NBLK];
__device__ unsigned int g_pcnt[NBLK];
// Arrival counter: zero-init at load; wraps back to 0 on the last block.
__device__ unsigned int g_arrive;

// d2 masked by m (m in {0,1}): bitwise AND with -m (all-ones or zero).
__device__ __forceinline__ float mask_and(float d2, int m) {
    return __int_as_float(__float_as_int(d2) & (-m));
}

// Release-ordered fetch-add on the arrival counter: orders this CTA's prior
// global stores (the partials) before the increment becomes visible, without
// a full MEMBAR.ALL.
__device__ __forceinline__ unsigned int arrive_release(unsigned int* p) {
    unsigned int old;
    asm volatile("atom.add.release.gpu.u32 %0, [%1], 1;"
                 : "=r"(old) : "l"(p) : "memory");
    return old;
}

__global__ void __launch_bounds__(NTHR, 3) mml_reduce_kernel(
    const float4* __restrict__ inp,
    const float4* __restrict__ tgt,
    const int4*   __restrict__ msk,
    int nvec,
    float* __restrict__ out)
{
    float s0 = 0.0f, s1 = 0.0f;
    unsigned int cnt = 0;

    const unsigned int stride = gridDim.x * blockDim.x;     // 227328
    const unsigned int uvec   = (unsigned int)nvec;          // 6291456
    unsigned int i = blockIdx.x * blockDim.x + threadIdx.x;

    // Exact per-thread work: counted unroll-2 loop, no per-iteration compare.
    unsigned int total = (i < uvec) ? ((uvec - 1 - i) / stride + 1u) : 0u;
    unsigned int pairs = total >> 1;
    unsigned int odd   = total & 1u;

    for (; pairs > 0; pairs--) {
        unsigned int j = i + stride;

        float4 a0 = __ldcs(&inp[i]);
        float4 a1 = __ldcs(&inp[j]);
        float4 b0 = __ldcs(&tgt[i]);
        float4 b1 = __ldcs(&tgt[j]);
        int4   m0 = __ldcs(&msk[i]);
        int4   m1 = __ldcs(&msk[j]);

        float d;
        d = a0.x - b0.x; s0 += mask_and(d * d, m0.x);
        d = a0.y - b0.y; s0 += mask_and(d * d, m0.y);
        d = a0.z - b0.z; s0 += mask_and(d * d, m0.z);
        d = a0.w - b0.w; s0 += mask_and(d * d, m0.w);

        d = a1.x - b1.x; s1 += mask_and(d * d, m1.x);
        d = a1.y - b1.y; s1 += mask_and(d * d, m1.y);
        d = a1.z - b1.z; s1 += mask_and(d * d, m1.z);
        d = a1.w - b1.w; s1 += mask_and(d * d, m1.w);

        cnt += (unsigned int)((m0.x + m0.y) + (m0.z + m0.w)
                            + (m1.x + m1.y) + (m1.z + m1.w));

        i = j + stride;
    }

    if (odd) {
        float4 a = __ldcs(&inp[i]);
        float4 b = __ldcs(&tgt[i]);
        int4   m = __ldcs(&msk[i]);
        float d;
        d = a.x - b.x; s0 += mask_and(d * d, m.x);
        d = a.y - b.y; s0 += mask_and(d * d, m.y);
        d = a.z - b.z; s1 += mask_and(d * d, m.z);
        d = a.w - b.w; s1 += mask_and(d * d, m.w);
        cnt += (unsigned int)((m.x + m.y) + (m.z + m.w));
    }

    float sum = s0 + s1;

    // Intra-block reduction (512 threads = 16 warps)
    #pragma unroll
    for (int off = 16; off > 0; off >>= 1) {
        sum += __shfl_down_sync(0xFFFFFFFFu, sum, off);
        cnt += __shfl_down_sync(0xFFFFFFFFu, cnt, off);
    }

    __shared__ float        s_sum[16];
    __shared__ unsigned int s_cnt[16];
    __shared__ bool         s_last;
    int lane = threadIdx.x & 31;
    int wid  = threadIdx.x >> 5;
    if (lane == 0) { s_sum[wid] = sum; s_cnt[wid] = cnt; }
    __syncthreads();

    if (wid == 0) {
        sum = (lane < 16) ? s_sum[lane] : 0.0f;
        cnt = (lane < 16) ? s_cnt[lane] : 0u;
        #pragma unroll
        for (int off = 8; off > 0; off >>= 1) {
            sum += __shfl_down_sync(0xFFFFFFFFu, sum, off);
            cnt += __shfl_down_sync(0xFFFFFFFFu, cnt, off);
        }
        if (lane == 0) {
            g_psum[blockIdx.x] = sum;
            g_pcnt[blockIdx.x] = cnt;
            // Release add: orders the two stores above before the count bump.
            unsigned int prev = arrive_release(&g_arrive);
            s_last = (prev == NBLK - 1);
            if (s_last) g_arrive = 0;  // reset for the next graph replay
        }
    }
    __syncthreads();

    if (!s_last) return;

    // Acquire fence: make all CTAs' released partials visible to this block.
    __threadfence();

    // Last block: reduce the 444 partials (L2-resident); one value per thread.
    double fsum = 0.0;
    unsigned long long fcnt = 0;
    if (threadIdx.x < NBLK) {
        fsum = (double)__ldcg(&g_psum[threadIdx.x]);
        fcnt = (unsigned long long)__ldcg(&g_pcnt[threadIdx.x]);
    }

    #pragma unroll
    for (int off = 16; off > 0; off >>= 1) {
        fsum += __shfl_down_sync(0xFFFFFFFFu, fsum, off);
        fcnt += __shfl_down_sync(0xFFFFFFFFu, fcnt, off);
    }

    __shared__ double             d_sum[16];
    __shared__ unsigned long long d_cnt[16];
    if (lane == 0) { d_sum[wid] = fsum; d_cnt[wid] = fcnt; }
    __syncthreads();

    if (wid == 0) {
        fsum = (lane < 16) ? d_sum[lane] : 0.0;
        fcnt = (lane < 16) ? d_cnt[lane] : 0ULL;
        #pragma unroll
        for (int off = 8; off > 0; off >>= 1) {
            fsum += __shfl_down_sync(0xFFFFFFFFu, fsum, off);
            fcnt += __shfl_down_sync(0xFFFFFFFFu, fcnt, off);
        }
        if (lane == 0) out[0] = (float)(fsum / (double)fcnt);
    }
}

extern "C" void kernel_launch(void* const* d_in, const int* in_sizes, int n_in,
                              void* d_out, int out_size)
{
    const float4* inp = (const float4*)d_in[0];
    const float4* tgt = (const float4*)d_in[1];
    const int4*   msk = (const int4*)d_in[2];
    float* out = (float*)d_out;

    int n = in_sizes[0];
    int nvec = n / 4;  // 25165824 % 4 == 0

    mml_reduce_kernel<<<NBLK, NTHR>>>(inp, tgt, msk, nvec, out);
}

// round 13
// speedup vs baseline: 1.0238x; 1.0238x over previous
#include <cuda_runtime.h>
#include <cstdint>

#define NBLK 444    // 148 SMs * 3 CTAs of 512 threads — 48 warps/SM, one wave
#define NTHR 512

// Per-block partials — every slot written on every call; no zeroing needed.
__device__ float        g_psum[NBLK];
__device__ unsigned int g_pcnt[NBLK];
// Arrival counter: zero-init at load; reset to 0 by the last block each call.
__device__ unsigned int g_arrive;

// d2 masked by m (m in {0,1}): bitwise AND with -m (all-ones or zero).
__device__ __forceinline__ float mask_and(float d2, int m) {
    return __int_as_float(__float_as_int(d2) & (-m));
}

// Release-ordered fetch-add: orders this CTA's prior global stores (the
// partials) before the increment becomes visible. No full MEMBAR.
__device__ __forceinline__ unsigned int arrive_release(unsigned int* p) {
    unsigned int old;
    asm volatile("atom.add.release.gpu.u32 %0, [%1], 1;"
                 : "=r"(old) : "l"(p) : "memory");
    return old;
}

// Acquire-ordered load: synchronizes-with the release-adds above, ordering
// the subsequent partial reads without a MEMBAR.
__device__ __forceinline__ unsigned int load_acquire(const unsigned int* p) {
    unsigned int v;
    asm volatile("ld.acquire.gpu.u32 %0, [%1];"
                 : "=r"(v) : "l"(p) : "memory");
    return v;
}

__global__ void __launch_bounds__(NTHR, 3) mml_reduce_kernel(
    const float4* __restrict__ inp,
    const float4* __restrict__ tgt,
    const int4*   __restrict__ msk,
    int nvec,
    float* __restrict__ out)
{
    float s0 = 0.0f, s1 = 0.0f;
    unsigned int cnt = 0;

    const unsigned int stride = gridDim.x * blockDim.x;     // 227328
    const unsigned int uvec   = (unsigned int)nvec;          // 6291456
    unsigned int i = blockIdx.x * blockDim.x + threadIdx.x;

    // Exact per-thread work: counted unroll-2 loop, no per-iteration compare.
    unsigned int total = (i < uvec) ? ((uvec - 1 - i) / stride + 1u) : 0u;
    unsigned int pairs = total >> 1;
    unsigned int odd   = total & 1u;

    for (; pairs > 0; pairs--) {
        unsigned int j = i + stride;

        float4 a0 = __ldcs(&inp[i]);
        float4 a1 = __ldcs(&inp[j]);
        float4 b0 = __ldcs(&tgt[i]);
        float4 b1 = __ldcs(&tgt[j]);
        int4   m0 = __ldcs(&msk[i]);
        int4   m1 = __ldcs(&msk[j]);

        float d;
        d = a0.x - b0.x; s0 += mask_and(d * d, m0.x);
        d = a0.y - b0.y; s0 += mask_and(d * d, m0.y);
        d = a0.z - b0.z; s0 += mask_and(d * d, m0.z);
        d = a0.w - b0.w; s0 += mask_and(d * d, m0.w);

        d = a1.x - b1.x; s1 += mask_and(d * d, m1.x);
        d = a1.y - b1.y; s1 += mask_and(d * d, m1.y);
        d = a1.z - b1.z; s1 += mask_and(d * d, m1.z);
        d = a1.w - b1.w; s1 += mask_and(d * d, m1.w);

        cnt += (unsigned int)((m0.x + m0.y) + (m0.z + m0.w)
                            + (m1.x + m1.y) + (m1.z + m1.w));

        i = j + stride;
    }

    if (odd) {
        float4 a = __ldcs(&inp[i]);
        float4 b = __ldcs(&tgt[i]);
        int4   m = __ldcs(&msk[i]);
        float d;
        d = a.x - b.x; s0 += mask_and(d * d, m.x);
        d = a.y - b.y; s0 += mask_and(d * d, m.y);
        d = a.z - b.z; s1 += mask_and(d * d, m.z);
        d = a.w - b.w; s1 += mask_and(d * d, m.w);
        cnt += (unsigned int)((m.x + m.y) + (m.z + m.w));
    }

    float sum = s0 + s1;

    // Intra-block reduction (512 threads = 16 warps)
    #pragma unroll
    for (int off = 16; off > 0; off >>= 1) {
        sum += __shfl_down_sync(0xFFFFFFFFu, sum, off);
        cnt += __shfl_down_sync(0xFFFFFFFFu, cnt, off);
    }

    __shared__ float        s_sum[16];
    __shared__ unsigned int s_cnt[16];
    __shared__ bool         s_last;
    int lane = threadIdx.x & 31;
    int wid  = threadIdx.x >> 5;
    if (lane == 0) { s_sum[wid] = sum; s_cnt[wid] = cnt; }
    __syncthreads();

    if (wid == 0) {
        sum = (lane < 16) ? s_sum[lane] : 0.0f;
        cnt = (lane < 16) ? s_cnt[lane] : 0u;
        #pragma unroll
        for (int off = 8; off > 0; off >>= 1) {
            sum += __shfl_down_sync(0xFFFFFFFFu, sum, off);
            cnt += __shfl_down_sync(0xFFFFFFFFu, cnt, off);
        }
        if (lane == 0) {
            g_psum[blockIdx.x] = sum;
            g_pcnt[blockIdx.x] = cnt;
            unsigned int prev = arrive_release(&g_arrive);
            s_last = (prev == NBLK - 1);
            if (s_last) {
                // Acquire pairs with all 444 release-adds; orders partial reads.
                (void)load_acquire(&g_arrive);
                g_arrive = 0;  // reset for the next graph replay
            }
        }
    }
    __syncthreads();

    if (!s_last) return;

    // Last block: reduce the 444 partials (L2-resident); one value per thread.
    double fsum = 0.0;
    unsigned long long fcnt = 0;
    if (threadIdx.x < NBLK) {
        fsum = (double)__ldcg(&g_psum[threadIdx.x]);
        fcnt = (unsigned long long)__ldcg(&g_pcnt[threadIdx.x]);
    }

    #pragma unroll
    for (int off = 16; off > 0; off >>= 1) {
        fsum += __shfl_down_sync(0xFFFFFFFFu, fsum, off);
        fcnt += __shfl_down_sync(0xFFFFFFFFu, fcnt, off);
    }

    __shared__ double             d_sum[16];
    __shared__ unsigned long long d_cnt[16];
    if (lane == 0) { d_sum[wid] = fsum; d_cnt[wid] = fcnt; }
    __syncthreads();

    if (wid == 0) {
        fsum = (lane < 16) ? d_sum[lane] : 0.0;
        fcnt = (lane < 16) ? d_cnt[lane] : 0ULL;
        #pragma unroll
        for (int off = 8; off > 0; off >>= 1) {
            fsum += __shfl_down_sync(0xFFFFFFFFu, fsum, off);
            fcnt += __shfl_down_sync(0xFFFFFFFFu, fcnt, off);
        }
        if (lane == 0) out[0] = (float)(fsum / (double)fcnt);
    }
}

extern "C" void kernel_launch(void* const* d_in, const int* in_sizes, int n_in,
                              void* d_out, int out_size)
{
    const float4* inp = (const float4*)d_in[0];
    const float4* tgt = (const float4*)d_in[1];
    const int4*   msk = (const int4*)d_in[2];
    float* out = (float*)d_out;

    int n = in_sizes[0];
    int nvec = n / 4;  // 25165824 % 4 == 0

    mml_reduce_kernel<<<NBLK, NTHR>>>(inp, tgt, msk, nvec, out);
}